// round 2
// baseline (speedup 1.0000x reference)
#include <cuda_runtime.h>
#include <math.h>
#include <stdint.h>

// Problem dims (fixed for this problem instance)
#define N_TOK 4096
#define DIM   1024
#define NEXP  8
#define FDIM  2048
#define NPAIR (2*N_TOK)

// ---------------- device scratch (no allocations allowed) ----------------
__device__ int   g_cnt[NEXP];
__device__ int   g_off[NEXP];
__device__ int   g_bucket[NEXP * N_TOK];      // packed: token*2 + slot
__device__ float g_pairw[NPAIR];              // combine weight per (token,slot)
__device__ float g_h[(size_t)NPAIR * FDIM];   // 64 MB hidden activations
__device__ float g_y[(size_t)NPAIR * DIM];    // 32 MB per-pair outputs

// ---------------- kernel 0: zero expert counters ----------------
__global__ void zero_kernel() {
    if (threadIdx.x < NEXP) g_cnt[threadIdx.x] = 0;
}

// ---------------- kernel 1: gating (softmax -> top2 -> softmax) ----------
// one warp per token
__global__ void gate_kernel(const float* __restrict__ x,
                            const float* __restrict__ gw,
                            const float* __restrict__ gb) {
    int tok  = (blockIdx.x * blockDim.x + threadIdx.x) >> 5;
    int lane = threadIdx.x & 31;
    if (tok >= N_TOK) return;
    const float* xr = x + (size_t)tok * DIM;

    float acc[NEXP];
#pragma unroll
    for (int e = 0; e < NEXP; e++) acc[e] = 0.f;

    for (int d = lane; d < DIM; d += 32) {
        float xv = xr[d];
        const float4* g4 = reinterpret_cast<const float4*>(gw + (size_t)d * NEXP);
        float4 a = g4[0], b = g4[1];
        acc[0] += xv * a.x; acc[1] += xv * a.y; acc[2] += xv * a.z; acc[3] += xv * a.w;
        acc[4] += xv * b.x; acc[5] += xv * b.y; acc[6] += xv * b.z; acc[7] += xv * b.w;
    }
#pragma unroll
    for (int e = 0; e < NEXP; e++) {
#pragma unroll
        for (int s = 16; s > 0; s >>= 1)
            acc[e] += __shfl_xor_sync(0xffffffffu, acc[e], s);
    }

    if (lane == 0) {
        float lg[NEXP];
        float mx = -1e30f;
#pragma unroll
        for (int e = 0; e < NEXP; e++) { lg[e] = acc[e] + gb[e]; mx = fmaxf(mx, lg[e]); }
        float sum = 0.f;
#pragma unroll
        for (int e = 0; e < NEXP; e++) { lg[e] = expf(lg[e] - mx); sum += lg[e]; }
        float inv = 1.f / sum;
#pragma unroll
        for (int e = 0; e < NEXP; e++) lg[e] *= inv;   // gate_scores (probabilities)

        // top-2 (strict > keeps lowest index on ties, matching jax.lax.top_k)
        int i0 = 0;
#pragma unroll
        for (int e = 1; e < NEXP; e++) if (lg[e] > lg[i0]) i0 = e;
        int i1 = -1;
#pragma unroll
        for (int e = 0; e < NEXP; e++)
            if (e != i0 && (i1 < 0 || lg[e] > lg[i1])) i1 = e;

        // softmax over the two selected probabilities (v0 >= v1)
        float v0 = lg[i0], v1 = lg[i1];
        float e1 = expf(v1 - v0);
        float is2 = 1.f / (1.f + e1);
        g_pairw[tok * 2 + 0] = is2;
        g_pairw[tok * 2 + 1] = e1 * is2;

        int p0 = atomicAdd(&g_cnt[i0], 1);
        g_bucket[i0 * N_TOK + p0] = tok * 2 + 0;
        int p1 = atomicAdd(&g_cnt[i1], 1);
        g_bucket[i1 * N_TOK + p1] = tok * 2 + 1;
    }
}

// ---------------- kernel 2: prefix sum of counts ----------------
__global__ void prefix_kernel() {
    int s = 0;
#pragma unroll
    for (int e = 0; e < NEXP; e++) { g_off[e] = s; s += g_cnt[e]; }
}

// ---------------- grouped SGEMM config ----------------
// BM=BN=128, BK=16, 256 threads, 8x8 per thread, double-buffered smem.
#define BM 128
#define BN 128
#define BK 16
#define APAD 4

// ---------------- kernel 3: H = relu(X_gathered @ w1[e] + b1[e]) ---------
__global__ void __launch_bounds__(256, 2)
gemm1_kernel(const float* __restrict__ x,
             const float* __restrict__ w1,
             const float* __restrict__ b1) {
    const int e   = blockIdx.z;
    const int cnt = g_cnt[e];
    const int m0  = blockIdx.y * BM;
    if (m0 >= cnt) return;
    const int n0   = blockIdx.x * BN;
    const int base = g_off[e];
    const int tid  = threadIdx.x;

    __shared__ float As[2][BK][BM + APAD];
    __shared__ float Bs[2][BK][BN];

    // A-load mapping: 2 gathered rows per thread, 4 consecutive k per row
    const int ar0 = tid >> 2;            // 0..63
    const int ar1 = ar0 + 64;
    const int ac4 = (tid & 3) * 4;       // 0,4,8,12
    const int t0  = g_bucket[e * N_TOK + min(m0 + ar0, cnt - 1)] >> 1;
    const int t1  = g_bucket[e * N_TOK + min(m0 + ar1, cnt - 1)] >> 1;
    const float* aptr0 = x + (size_t)t0 * DIM + ac4;
    const float* aptr1 = x + (size_t)t1 * DIM + ac4;

    // B-load mapping: 2 rows of 4 floats per thread
    const int brr = tid >> 5;            // 0..7
    const int bc4 = (tid & 31) * 4;
    const float* bptr = w1 + (size_t)e * DIM * FDIM + (size_t)brr * FDIM + n0 + bc4;

    const int ty = tid >> 4, tx = tid & 15;

    float acc[8][8];
#pragma unroll
    for (int i = 0; i < 8; i++)
#pragma unroll
        for (int j = 0; j < 8; j++) acc[i][j] = 0.f;

    // prologue: tile 0 -> smem[0]
    float4 a0 = *(const float4*)(aptr0);
    float4 a1 = *(const float4*)(aptr1);
    float4 b0 = *(const float4*)(bptr);
    float4 b1v = *(const float4*)(bptr + (size_t)8 * FDIM);
    As[0][ac4 + 0][ar0] = a0.x; As[0][ac4 + 1][ar0] = a0.y;
    As[0][ac4 + 2][ar0] = a0.z; As[0][ac4 + 3][ar0] = a0.w;
    As[0][ac4 + 0][ar1] = a1.x; As[0][ac4 + 1][ar1] = a1.y;
    As[0][ac4 + 2][ar1] = a1.z; As[0][ac4 + 3][ar1] = a1.w;
    *(float4*)&Bs[0][brr][bc4] = b0;
    *(float4*)&Bs[0][brr + 8][bc4] = b1v;
    __syncthreads();

    const int KT = DIM / BK;
    for (int kt = 0; kt < KT; kt++) {
        const int buf = kt & 1;
        const bool more = (kt + 1 < KT);
        if (more) {
            const int ko = (kt + 1) * BK;
            a0  = *(const float4*)(aptr0 + ko);
            a1  = *(const float4*)(aptr1 + ko);
            b0  = *(const float4*)(bptr + (size_t)ko * FDIM);
            b1v = *(const float4*)(bptr + (size_t)(ko + 8) * FDIM);
        }
#pragma unroll
        for (int k = 0; k < BK; k++) {
            float4 ra0 = *(const float4*)&As[buf][k][ty * 8];
            float4 ra1 = *(const float4*)&As[buf][k][ty * 8 + 4];
            float4 rb0 = *(const float4*)&Bs[buf][k][tx * 8];
            float4 rb1 = *(const float4*)&Bs[buf][k][tx * 8 + 4];
            float am[8] = {ra0.x, ra0.y, ra0.z, ra0.w, ra1.x, ra1.y, ra1.z, ra1.w};
            float bn[8] = {rb0.x, rb0.y, rb0.z, rb0.w, rb1.x, rb1.y, rb1.z, rb1.w};
#pragma unroll
            for (int i = 0; i < 8; i++)
#pragma unroll
                for (int j = 0; j < 8; j++)
                    acc[i][j] += am[i] * bn[j];
        }
        if (more) {
            const int nb = buf ^ 1;
            As[nb][ac4 + 0][ar0] = a0.x; As[nb][ac4 + 1][ar0] = a0.y;
            As[nb][ac4 + 2][ar0] = a0.z; As[nb][ac4 + 3][ar0] = a0.w;
            As[nb][ac4 + 0][ar1] = a1.x; As[nb][ac4 + 1][ar1] = a1.y;
            As[nb][ac4 + 2][ar1] = a1.z; As[nb][ac4 + 3][ar1] = a1.w;
            *(float4*)&Bs[nb][brr][bc4] = b0;
            *(float4*)&Bs[nb][brr + 8][bc4] = b1v;
            __syncthreads();
        }
    }

    // epilogue: +b1, relu, store to g_h
    const float* brow = b1 + (size_t)e * FDIM + n0 + tx * 8;
    float4 bb0 = *(const float4*)(brow);
    float4 bb1 = *(const float4*)(brow + 4);
#pragma unroll
    for (int i = 0; i < 8; i++) {
        int gr = m0 + ty * 8 + i;
        if (gr < cnt) {
            float* hrow = g_h + (size_t)(base + gr) * FDIM + n0 + tx * 8;
            float4 v0, v1;
            v0.x = fmaxf(acc[i][0] + bb0.x, 0.f);
            v0.y = fmaxf(acc[i][1] + bb0.y, 0.f);
            v0.z = fmaxf(acc[i][2] + bb0.z, 0.f);
            v0.w = fmaxf(acc[i][3] + bb0.w, 0.f);
            v1.x = fmaxf(acc[i][4] + bb1.x, 0.f);
            v1.y = fmaxf(acc[i][5] + bb1.y, 0.f);
            v1.z = fmaxf(acc[i][6] + bb1.z, 0.f);
            v1.w = fmaxf(acc[i][7] + bb1.w, 0.f);
            *(float4*)(hrow)     = v0;
            *(float4*)(hrow + 4) = v1;
        }
    }
}

// ---------------- kernel 4: Y = (H @ w2[e] + b2[e]) * weight -------------
__global__ void __launch_bounds__(256, 2)
gemm2_kernel(const float* __restrict__ w2,
             const float* __restrict__ b2) {
    const int e   = blockIdx.z;
    const int cnt = g_cnt[e];
    const int m0  = blockIdx.y * BM;
    if (m0 >= cnt) return;
    const int n0   = blockIdx.x * BN;
    const int base = g_off[e];
    const int tid  = threadIdx.x;

    __shared__ float As[2][BK][BM + APAD];
    __shared__ float Bs[2][BK][BN];

    const int ar0 = tid >> 2;
    const int ar1 = ar0 + 64;
    const int ac4 = (tid & 3) * 4;
    const int hr0 = base + min(m0 + ar0, cnt - 1);
    const int hr1 = base + min(m0 + ar1, cnt - 1);
    const float* aptr0 = g_h + (size_t)hr0 * FDIM + ac4;
    const float* aptr1 = g_h + (size_t)hr1 * FDIM + ac4;

    const int brr = tid >> 5;
    const int bc4 = (tid & 31) * 4;
    const float* bptr = w2 + (size_t)e * FDIM * DIM + (size_t)brr * DIM + n0 + bc4;

    const int ty = tid >> 4, tx = tid & 15;

    float acc[8][8];
#pragma unroll
    for (int i = 0; i < 8; i++)
#pragma unroll
        for (int j = 0; j < 8; j++) acc[i][j] = 0.f;

    float4 a0 = *(const float4*)(aptr0);
    float4 a1 = *(const float4*)(aptr1);
    float4 b0 = *(const float4*)(bptr);
    float4 b1v = *(const float4*)(bptr + (size_t)8 * DIM);
    As[0][ac4 + 0][ar0] = a0.x; As[0][ac4 + 1][ar0] = a0.y;
    As[0][ac4 + 2][ar0] = a0.z; As[0][ac4 + 3][ar0] = a0.w;
    As[0][ac4 + 0][ar1] = a1.x; As[0][ac4 + 1][ar1] = a1.y;
    As[0][ac4 + 2][ar1] = a1.z; As[0][ac4 + 3][ar1] = a1.w;
    *(float4*)&Bs[0][brr][bc4] = b0;
    *(float4*)&Bs[0][brr + 8][bc4] = b1v;
    __syncthreads();

    const int KT = FDIM / BK;
    for (int kt = 0; kt < KT; kt++) {
        const int buf = kt & 1;
        const bool more = (kt + 1 < KT);
        if (more) {
            const int ko = (kt + 1) * BK;
            a0  = *(const float4*)(aptr0 + ko);
            a1  = *(const float4*)(aptr1 + ko);
            b0  = *(const float4*)(bptr + (size_t)ko * DIM);
            b1v = *(const float4*)(bptr + (size_t)(ko + 8) * DIM);
        }
#pragma unroll
        for (int k = 0; k < BK; k++) {
            float4 ra0 = *(const float4*)&As[buf][k][ty * 8];
            float4 ra1 = *(const float4*)&As[buf][k][ty * 8 + 4];
            float4 rb0 = *(const float4*)&Bs[buf][k][tx * 8];
            float4 rb1 = *(const float4*)&Bs[buf][k][tx * 8 + 4];
            float am[8] = {ra0.x, ra0.y, ra0.z, ra0.w, ra1.x, ra1.y, ra1.z, ra1.w};
            float bn[8] = {rb0.x, rb0.y, rb0.z, rb0.w, rb1.x, rb1.y, rb1.z, rb1.w};
#pragma unroll
            for (int i = 0; i < 8; i++)
#pragma unroll
                for (int j = 0; j < 8; j++)
                    acc[i][j] += am[i] * bn[j];
        }
        if (more) {
            const int nb = buf ^ 1;
            As[nb][ac4 + 0][ar0] = a0.x; As[nb][ac4 + 1][ar0] = a0.y;
            As[nb][ac4 + 2][ar0] = a0.z; As[nb][ac4 + 3][ar0] = a0.w;
            As[nb][ac4 + 0][ar1] = a1.x; As[nb][ac4 + 1][ar1] = a1.y;
            As[nb][ac4 + 2][ar1] = a1.z; As[nb][ac4 + 3][ar1] = a1.w;
            *(float4*)&Bs[nb][brr][bc4] = b0;
            *(float4*)&Bs[nb][brr + 8][bc4] = b1v;
            __syncthreads();
        }
    }

    // epilogue: (+b2) * combine-weight, store to g_y[pair]
    const float* brow = b2 + (size_t)e * DIM + n0 + tx * 8;
    float4 bb0 = *(const float4*)(brow);
    float4 bb1 = *(const float4*)(brow + 4);
#pragma unroll
    for (int i = 0; i < 8; i++) {
        int gr = m0 + ty * 8 + i;
        if (gr < cnt) {
            int p   = g_bucket[e * N_TOK + gr];
            float w = g_pairw[p];
            float* yrow = g_y + (size_t)p * DIM + n0 + tx * 8;
            float4 v0, v1;
            v0.x = (acc[i][0] + bb0.x) * w;
            v0.y = (acc[i][1] + bb0.y) * w;
            v0.z = (acc[i][2] + bb0.z) * w;
            v0.w = (acc[i][3] + bb0.w) * w;
            v1.x = (acc[i][4] + bb1.x) * w;
            v1.y = (acc[i][5] + bb1.y) * w;
            v1.z = (acc[i][6] + bb1.z) * w;
            v1.w = (acc[i][7] + bb1.w) * w;
            *(float4*)(yrow)     = v0;
            *(float4*)(yrow + 4) = v1;
        }
    }
}

// ---------------- kernel 5: out[n] = y[n,slot0] + y[n,slot1] -------------
// one block per token row, 256 threads -> 4 floats each
__global__ void combine_kernel(float* __restrict__ out) {
    const int n = blockIdx.x;
    const int c = threadIdx.x * 4;
    const float4 a = *(const float4*)(g_y + (size_t)(2 * n) * DIM + c);
    const float4 b = *(const float4*)(g_y + (size_t)(2 * n + 1) * DIM + c);
    float4 o;
    o.x = a.x + b.x; o.y = a.y + b.y; o.z = a.z + b.z; o.w = a.w + b.w;
    *(float4*)(out + (size_t)n * DIM + c) = o;
}

// ---------------- launch ----------------
extern "C" void kernel_launch(void* const* d_in, const int* in_sizes, int n_in,
                              void* d_out, int out_size) {
    const float* x  = (const float*)d_in[0];
    const float* gw = (const float*)d_in[1];
    const float* gb = (const float*)d_in[2];
    const float* w1 = (const float*)d_in[3];
    const float* b1 = (const float*)d_in[4];
    const float* w2 = (const float*)d_in[5];
    const float* b2 = (const float*)d_in[6];
    float* out = (float*)d_out;

    zero_kernel<<<1, 32>>>();
    gate_kernel<<<N_TOK / 8, 256>>>(x, gw, gb);
    prefix_kernel<<<1, 1>>>();
    gemm1_kernel<<<dim3(FDIM / BN, N_TOK / BM, NEXP), 256>>>(x, w1, b1);
    gemm2_kernel<<<dim3(DIM / BN, N_TOK / BM, NEXP), 256>>>(w2, b2);
    combine_kernel<<<N_TOK, DIM / 4>>>(out);
}

// round 4
// speedup vs baseline: 1.6119x; 1.6119x over previous
#include <cuda_runtime.h>
#include <cuda_bf16.h>
#include <math.h>
#include <stdint.h>

#define N_TOK 4096
#define DIM   1024
#define NEXP  8
#define FDIM  2048
#define NPAIR (2*N_TOK)

// ---------------- device scratch (total ~80.4 MB, under the proven 96MB) ----
__device__ int   g_cnt[NEXP];
__device__ int   g_off[NEXP];
__device__ int   g_bucket[NEXP * N_TOK];
__device__ float g_pairw[NPAIR];
__device__ __nv_bfloat16 g_xh[(size_t)N_TOK * DIM];   // 8 MB
__device__ __nv_bfloat16 g_xl[(size_t)N_TOK * DIM];   // 8 MB
__device__ __nv_bfloat16 g_hh[(size_t)NPAIR * FDIM];  // 32 MB
__device__ __nv_bfloat16 g_hl[(size_t)NPAIR * FDIM];  // 32 MB

// ---------------- kernel 0: zero expert counters ----------------
__global__ void zero_kernel() {
    if (threadIdx.x < NEXP) g_cnt[threadIdx.x] = 0;
}

// ---------------- kernel 1: gating ----------------
__global__ void gate_kernel(const float* __restrict__ x,
                            const float* __restrict__ gw,
                            const float* __restrict__ gb) {
    int tok  = (blockIdx.x * blockDim.x + threadIdx.x) >> 5;
    int lane = threadIdx.x & 31;
    if (tok >= N_TOK) return;
    const float* xr = x + (size_t)tok * DIM;

    float acc[NEXP];
#pragma unroll
    for (int e = 0; e < NEXP; e++) acc[e] = 0.f;
    for (int d = lane; d < DIM; d += 32) {
        float xv = xr[d];
        const float4* g4 = reinterpret_cast<const float4*>(gw + (size_t)d * NEXP);
        float4 a = g4[0], b = g4[1];
        acc[0] += xv * a.x; acc[1] += xv * a.y; acc[2] += xv * a.z; acc[3] += xv * a.w;
        acc[4] += xv * b.x; acc[5] += xv * b.y; acc[6] += xv * b.z; acc[7] += xv * b.w;
    }
#pragma unroll
    for (int e = 0; e < NEXP; e++) {
#pragma unroll
        for (int s = 16; s > 0; s >>= 1)
            acc[e] += __shfl_xor_sync(0xffffffffu, acc[e], s);
    }
    if (lane == 0) {
        float lg[NEXP];
        float mx = -1e30f;
#pragma unroll
        for (int e = 0; e < NEXP; e++) { lg[e] = acc[e] + gb[e]; mx = fmaxf(mx, lg[e]); }
        float sum = 0.f;
#pragma unroll
        for (int e = 0; e < NEXP; e++) { lg[e] = expf(lg[e] - mx); sum += lg[e]; }
        float inv = 1.f / sum;
#pragma unroll
        for (int e = 0; e < NEXP; e++) lg[e] *= inv;

        int i0 = 0;
#pragma unroll
        for (int e = 1; e < NEXP; e++) if (lg[e] > lg[i0]) i0 = e;
        int i1 = -1;
#pragma unroll
        for (int e = 0; e < NEXP; e++)
            if (e != i0 && (i1 < 0 || lg[e] > lg[i1])) i1 = e;

        float e1 = expf(lg[i1] - lg[i0]);
        float is2 = 1.f / (1.f + e1);
        g_pairw[tok * 2 + 0] = is2;
        g_pairw[tok * 2 + 1] = e1 * is2;

        int p0 = atomicAdd(&g_cnt[i0], 1);
        g_bucket[i0 * N_TOK + p0] = tok * 2 + 0;
        int p1 = atomicAdd(&g_cnt[i1], 1);
        g_bucket[i1 * N_TOK + p1] = tok * 2 + 1;
    }
}

// ---------------- kernel 2: prefix ----------------
__global__ void prefix_kernel() {
    int s = 0;
#pragma unroll
    for (int e = 0; e < NEXP; e++) { g_off[e] = s; s += g_cnt[e]; }
}

// ---------------- kernel 3: x -> bf16 hi/lo planes ----------------
__global__ void convx_kernel(const float* __restrict__ x) {
    size_t i = ((size_t)blockIdx.x * blockDim.x + threadIdx.x) * 4;
    float4 v = *(const float4*)(x + i);
    __nv_bfloat16 h0 = __float2bfloat16(v.x), h1 = __float2bfloat16(v.y);
    __nv_bfloat16 h2 = __float2bfloat16(v.z), h3 = __float2bfloat16(v.w);
    ushort4 hv = make_ushort4(__bfloat16_as_ushort(h0), __bfloat16_as_ushort(h1),
                              __bfloat16_as_ushort(h2), __bfloat16_as_ushort(h3));
    ushort4 lv = make_ushort4(
        __bfloat16_as_ushort(__float2bfloat16(v.x - __bfloat162float(h0))),
        __bfloat16_as_ushort(__float2bfloat16(v.y - __bfloat162float(h1))),
        __bfloat16_as_ushort(__float2bfloat16(v.z - __bfloat162float(h2))),
        __bfloat16_as_ushort(__float2bfloat16(v.w - __bfloat162float(h3))));
    *(ushort4*)(g_xh + i) = hv;
    *(ushort4*)(g_xl + i) = lv;
}

// ---------------- kernel 4: zero output ----------------
__global__ void zeroout_kernel(float* __restrict__ out) {
    size_t i = ((size_t)blockIdx.x * blockDim.x + threadIdx.x) * 4;
    float4 z = make_float4(0.f, 0.f, 0.f, 0.f);
    *(float4*)(out + i) = z;
}

// ---------------- GEMM config ----------------
#define BM 128
#define BN 128
#define BK 32
#define LDA 40   // bf16 elements per A smem row (padded)
#define BKP 36   // u32 per B smem row (padded)

__device__ __forceinline__ void mma_bf16(float (&c)[4], const uint32_t* a, const uint32_t* b) {
    asm volatile(
        "mma.sync.aligned.m16n8k16.row.col.f32.bf16.bf16.f32 "
        "{%0,%1,%2,%3}, {%4,%5,%6,%7}, {%8,%9}, {%0,%1,%2,%3};"
        : "+f"(c[0]), "+f"(c[1]), "+f"(c[2]), "+f"(c[3])
        : "r"(a[0]), "r"(a[1]), "r"(a[2]), "r"(a[3]), "r"(b[0]), "r"(b[1]));
}

// pack fp32 -> (hi_bf16 truncated | lo_bf16 << 16); split is error-free.
__device__ __forceinline__ uint32_t pack_hilo(float v) {
    uint32_t u = __float_as_uint(v);
    float hi_f = __uint_as_float(u & 0xffff0000u);
    float lo   = v - hi_f;                       // exact
    uint32_t lo_b = (uint32_t)__bfloat16_as_ushort(__float2bfloat16(lo));
    return (u >> 16) | (lo_b << 16);
}

// ---------------- kernel 5: H = relu(Xg @ w1 + b1) -> bf16 hi/lo ----------
__global__ void __launch_bounds__(256)
gemm1_mma(const float* __restrict__ w1, const float* __restrict__ b1) {
    const int e   = blockIdx.z;
    const int cnt = g_cnt[e];
    const int m0  = blockIdx.y * BM;
    if (m0 >= cnt) return;
    const int n0   = blockIdx.x * BN;
    const int base = g_off[e];
    const int tid  = threadIdx.x;
    const int wid  = tid >> 5, lane = tid & 31;

    __shared__ __nv_bfloat16 Ah[BM * LDA], Al[BM * LDA];
    __shared__ uint32_t Bp[BN * BKP];

    // A fill mapping: one row per 2 threads
    const int ar  = tid >> 1;            // 0..127
    const int akc = (tid & 1) * 16;      // 0 / 16 (bf16 elements)
    const int t0  = g_bucket[e * N_TOK + min(m0 + ar, cnt - 1)] >> 1;
    const __nv_bfloat16* pAh = g_xh + (size_t)t0 * DIM + akc;
    const __nv_bfloat16* pAl = g_xl + (size_t)t0 * DIM + akc;

    // B fill mapping: warp handles 4 k-rows, lane covers 16 n (4 x float4)
    const int bkr = wid * 4 + (lane >> 3);   // 0..31
    const int bnl = (lane & 7) * 4;          // 0..28
    const float* pB = w1 + (size_t)e * DIM * FDIM + (size_t)bkr * FDIM + n0 + bnl;

    const int wm = (wid & 1) * 64, wn = (wid >> 1) * 32;
    const int gq = lane >> 2, tq = lane & 3;

    float acc[4][4][4];
#pragma unroll
    for (int i = 0; i < 4; i++)
#pragma unroll
        for (int j = 0; j < 4; j++)
#pragma unroll
            for (int q = 0; q < 4; q++) acc[i][j][q] = 0.f;

    uint4 sah0, sah1, sal0, sal1;
    float4 sb[4];

    // prologue load (k=0)
    sah0 = *(const uint4*)(pAh);     sah1 = *(const uint4*)(pAh + 8);
    sal0 = *(const uint4*)(pAl);     sal1 = *(const uint4*)(pAl + 8);
#pragma unroll
    for (int i = 0; i < 4; i++) sb[i] = *(const float4*)(pB + (size_t)0 * FDIM + 32 * i);

    // prologue store
    *(uint4*)&Ah[ar * LDA + akc]     = sah0; *(uint4*)&Ah[ar * LDA + akc + 8] = sah1;
    *(uint4*)&Al[ar * LDA + akc]     = sal0; *(uint4*)&Al[ar * LDA + akc + 8] = sal1;
#pragma unroll
    for (int i = 0; i < 4; i++) {
        Bp[(bnl + 32 * i + 0) * BKP + bkr] = pack_hilo(sb[i].x);
        Bp[(bnl + 32 * i + 1) * BKP + bkr] = pack_hilo(sb[i].y);
        Bp[(bnl + 32 * i + 2) * BKP + bkr] = pack_hilo(sb[i].z);
        Bp[(bnl + 32 * i + 3) * BKP + bkr] = pack_hilo(sb[i].w);
    }
    __syncthreads();

    const int KT = DIM / BK;
    for (int kt = 0; kt < KT; kt++) {
        const bool more = (kt + 1 < KT);
        if (more) {
            const int ko = (kt + 1) * BK;
            sah0 = *(const uint4*)(pAh + ko);     sah1 = *(const uint4*)(pAh + ko + 8);
            sal0 = *(const uint4*)(pAl + ko);     sal1 = *(const uint4*)(pAl + ko + 8);
#pragma unroll
            for (int i = 0; i < 4; i++)
                sb[i] = *(const float4*)(pB + (size_t)ko * FDIM + 32 * i);
        }
#pragma unroll
        for (int ks = 0; ks < 2; ks++) {
            const int kb = ks * 16 + tq * 2;
            uint32_t bh[4][2], bl[4][2];
#pragma unroll
            for (int nt = 0; nt < 4; nt++) {
                const int nr = (wn + nt * 8 + gq) * BKP;
                uint2 q0 = *(const uint2*)&Bp[nr + kb];
                uint2 q1 = *(const uint2*)&Bp[nr + kb + 8];
                bh[nt][0] = __byte_perm(q0.x, q0.y, 0x5410);
                bl[nt][0] = __byte_perm(q0.x, q0.y, 0x7632);
                bh[nt][1] = __byte_perm(q1.x, q1.y, 0x5410);
                bl[nt][1] = __byte_perm(q1.x, q1.y, 0x7632);
            }
#pragma unroll
            for (int mt = 0; mt < 4; mt++) {
                const int aro  = (wm + mt * 16 + gq) * LDA;
                const int aro8 = aro + 8 * LDA;
                uint32_t ah[4] = {
                    *(const uint32_t*)&Ah[aro + kb],     *(const uint32_t*)&Ah[aro8 + kb],
                    *(const uint32_t*)&Ah[aro + kb + 8], *(const uint32_t*)&Ah[aro8 + kb + 8] };
                uint32_t al[4] = {
                    *(const uint32_t*)&Al[aro + kb],     *(const uint32_t*)&Al[aro8 + kb],
                    *(const uint32_t*)&Al[aro + kb + 8], *(const uint32_t*)&Al[aro8 + kb + 8] };
#pragma unroll
                for (int nt = 0; nt < 4; nt++) {
                    mma_bf16(acc[mt][nt], ah, bh[nt]);
                    mma_bf16(acc[mt][nt], ah, bl[nt]);
                    mma_bf16(acc[mt][nt], al, bh[nt]);
                }
            }
        }
        if (more) {
            __syncthreads();
            *(uint4*)&Ah[ar * LDA + akc]     = sah0; *(uint4*)&Ah[ar * LDA + akc + 8] = sah1;
            *(uint4*)&Al[ar * LDA + akc]     = sal0; *(uint4*)&Al[ar * LDA + akc + 8] = sal1;
#pragma unroll
            for (int i = 0; i < 4; i++) {
                Bp[(bnl + 32 * i + 0) * BKP + bkr] = pack_hilo(sb[i].x);
                Bp[(bnl + 32 * i + 1) * BKP + bkr] = pack_hilo(sb[i].y);
                Bp[(bnl + 32 * i + 2) * BKP + bkr] = pack_hilo(sb[i].z);
                Bp[(bnl + 32 * i + 3) * BKP + bkr] = pack_hilo(sb[i].w);
            }
            __syncthreads();
        }
    }

    // epilogue: +b1, relu, split to bf16 hi/lo planes
#pragma unroll
    for (int nt = 0; nt < 4; nt++) {
        const int nc = n0 + wn + nt * 8 + tq * 2;
        const float bb0 = b1[e * FDIM + nc];
        const float bb1 = b1[e * FDIM + nc + 1];
#pragma unroll
        for (int mt = 0; mt < 4; mt++) {
            const int rl = wm + mt * 16 + gq;
#pragma unroll
            for (int half = 0; half < 2; half++) {
                const int gr = m0 + rl + half * 8;
                if (gr < cnt) {
                    float v0 = fmaxf(acc[mt][nt][half * 2 + 0] + bb0, 0.f);
                    float v1 = fmaxf(acc[mt][nt][half * 2 + 1] + bb1, 0.f);
                    size_t o = (size_t)(base + gr) * FDIM + nc;
                    __nv_bfloat16 h0 = __float2bfloat16(v0), h1 = __float2bfloat16(v1);
                    __nv_bfloat162 hv; hv.x = h0; hv.y = h1;
                    __nv_bfloat162 lv;
                    lv.x = __float2bfloat16(v0 - __bfloat162float(h0));
                    lv.y = __float2bfloat16(v1 - __bfloat162float(h1));
                    *(__nv_bfloat162*)&g_hh[o] = hv;
                    *(__nv_bfloat162*)&g_hl[o] = lv;
                }
            }
        }
    }
}

// ---------------- kernel 6: out += (H @ w2 + b2) * pairw (atomic) --------
__global__ void __launch_bounds__(256)
gemm2_mma(const float* __restrict__ w2, const float* __restrict__ b2,
          float* __restrict__ out) {
    const int e   = blockIdx.z;
    const int cnt = g_cnt[e];
    const int m0  = blockIdx.y * BM;
    if (m0 >= cnt) return;
    const int n0   = blockIdx.x * BN;
    const int base = g_off[e];
    const int tid  = threadIdx.x;
    const int wid  = tid >> 5, lane = tid & 31;

    __shared__ __nv_bfloat16 Ah[BM * LDA], Al[BM * LDA];
    __shared__ uint32_t Bp[BN * BKP];

    const int ar  = tid >> 1;
    const int akc = (tid & 1) * 16;
    const int a0r = base + min(m0 + ar, cnt - 1);
    const __nv_bfloat16* pAh = g_hh + (size_t)a0r * FDIM + akc;
    const __nv_bfloat16* pAl = g_hl + (size_t)a0r * FDIM + akc;

    const int bkr = wid * 4 + (lane >> 3);
    const int bnl = (lane & 7) * 4;
    const float* pB = w2 + (size_t)e * FDIM * DIM + (size_t)bkr * DIM + n0 + bnl;

    const int wm = (wid & 1) * 64, wn = (wid >> 1) * 32;
    const int gq = lane >> 2, tq = lane & 3;

    float acc[4][4][4];
#pragma unroll
    for (int i = 0; i < 4; i++)
#pragma unroll
        for (int j = 0; j < 4; j++)
#pragma unroll
            for (int q = 0; q < 4; q++) acc[i][j][q] = 0.f;

    uint4 sah0, sah1, sal0, sal1;
    float4 sb[4];

    sah0 = *(const uint4*)(pAh);     sah1 = *(const uint4*)(pAh + 8);
    sal0 = *(const uint4*)(pAl);     sal1 = *(const uint4*)(pAl + 8);
#pragma unroll
    for (int i = 0; i < 4; i++) sb[i] = *(const float4*)(pB + (size_t)0 * DIM + 32 * i);

    *(uint4*)&Ah[ar * LDA + akc]     = sah0; *(uint4*)&Ah[ar * LDA + akc + 8] = sah1;
    *(uint4*)&Al[ar * LDA + akc]     = sal0; *(uint4*)&Al[ar * LDA + akc + 8] = sal1;
#pragma unroll
    for (int i = 0; i < 4; i++) {
        Bp[(bnl + 32 * i + 0) * BKP + bkr] = pack_hilo(sb[i].x);
        Bp[(bnl + 32 * i + 1) * BKP + bkr] = pack_hilo(sb[i].y);
        Bp[(bnl + 32 * i + 2) * BKP + bkr] = pack_hilo(sb[i].z);
        Bp[(bnl + 32 * i + 3) * BKP + bkr] = pack_hilo(sb[i].w);
    }
    __syncthreads();

    const int KT = FDIM / BK;
    for (int kt = 0; kt < KT; kt++) {
        const bool more = (kt + 1 < KT);
        if (more) {
            const int ko = (kt + 1) * BK;
            sah0 = *(const uint4*)(pAh + ko);     sah1 = *(const uint4*)(pAh + ko + 8);
            sal0 = *(const uint4*)(pAl + ko);     sal1 = *(const uint4*)(pAl + ko + 8);
#pragma unroll
            for (int i = 0; i < 4; i++)
                sb[i] = *(const float4*)(pB + (size_t)ko * DIM + 32 * i);
        }
#pragma unroll
        for (int ks = 0; ks < 2; ks++) {
            const int kb = ks * 16 + tq * 2;
            uint32_t bh[4][2], bl[4][2];
#pragma unroll
            for (int nt = 0; nt < 4; nt++) {
                const int nr = (wn + nt * 8 + gq) * BKP;
                uint2 q0 = *(const uint2*)&Bp[nr + kb];
                uint2 q1 = *(const uint2*)&Bp[nr + kb + 8];
                bh[nt][0] = __byte_perm(q0.x, q0.y, 0x5410);
                bl[nt][0] = __byte_perm(q0.x, q0.y, 0x7632);
                bh[nt][1] = __byte_perm(q1.x, q1.y, 0x5410);
                bl[nt][1] = __byte_perm(q1.x, q1.y, 0x7632);
            }
#pragma unroll
            for (int mt = 0; mt < 4; mt++) {
                const int aro  = (wm + mt * 16 + gq) * LDA;
                const int aro8 = aro + 8 * LDA;
                uint32_t ah[4] = {
                    *(const uint32_t*)&Ah[aro + kb],     *(const uint32_t*)&Ah[aro8 + kb],
                    *(const uint32_t*)&Ah[aro + kb + 8], *(const uint32_t*)&Ah[aro8 + kb + 8] };
                uint32_t al[4] = {
                    *(const uint32_t*)&Al[aro + kb],     *(const uint32_t*)&Al[aro8 + kb],
                    *(const uint32_t*)&Al[aro + kb + 8], *(const uint32_t*)&Al[aro8 + kb + 8] };
#pragma unroll
                for (int nt = 0; nt < 4; nt++) {
                    mma_bf16(acc[mt][nt], ah, bh[nt]);
                    mma_bf16(acc[mt][nt], ah, bl[nt]);
                    mma_bf16(acc[mt][nt], al, bh[nt]);
                }
            }
        }
        if (more) {
            __syncthreads();
            *(uint4*)&Ah[ar * LDA + akc]     = sah0; *(uint4*)&Ah[ar * LDA + akc + 8] = sah1;
            *(uint4*)&Al[ar * LDA + akc]     = sal0; *(uint4*)&Al[ar * LDA + akc + 8] = sal1;
#pragma unroll
            for (int i = 0; i < 4; i++) {
                Bp[(bnl + 32 * i + 0) * BKP + bkr] = pack_hilo(sb[i].x);
                Bp[(bnl + 32 * i + 1) * BKP + bkr] = pack_hilo(sb[i].y);
                Bp[(bnl + 32 * i + 2) * BKP + bkr] = pack_hilo(sb[i].z);
                Bp[(bnl + 32 * i + 3) * BKP + bkr] = pack_hilo(sb[i].w);
            }
            __syncthreads();
        }
    }

    // epilogue: (+b2) * combine weight, atomicAdd into out (2 adds/element,
    // fp32 add is commutative -> bitwise deterministic)
#pragma unroll
    for (int nt = 0; nt < 4; nt++) {
        const int nc = n0 + wn + nt * 8 + tq * 2;
        const float bb0 = b2[e * DIM + nc];
        const float bb1 = b2[e * DIM + nc + 1];
#pragma unroll
        for (int mt = 0; mt < 4; mt++) {
            const int rl = wm + mt * 16 + gq;
#pragma unroll
            for (int half = 0; half < 2; half++) {
                const int gr = m0 + rl + half * 8;
                if (gr < cnt) {
                    const int p = g_bucket[e * N_TOK + gr];
                    const float w = g_pairw[p];
                    float* orow = out + (size_t)(p >> 1) * DIM + nc;
                    atomicAdd(orow,     (acc[mt][nt][half * 2 + 0] + bb0) * w);
                    atomicAdd(orow + 1, (acc[mt][nt][half * 2 + 1] + bb1) * w);
                }
            }
        }
    }
}

// ---------------- launch ----------------
extern "C" void kernel_launch(void* const* d_in, const int* in_sizes, int n_in,
                              void* d_out, int out_size) {
    const float* x  = (const float*)d_in[0];
    const float* gw = (const float*)d_in[1];
    const float* gb = (const float*)d_in[2];
    const float* w1 = (const float*)d_in[3];
    const float* b1 = (const float*)d_in[4];
    const float* w2 = (const float*)d_in[5];
    const float* b2 = (const float*)d_in[6];
    float* out = (float*)d_out;

    zero_kernel<<<1, 32>>>();
    gate_kernel<<<N_TOK / 8, 256>>>(x, gw, gb);
    prefix_kernel<<<1, 1>>>();
    convx_kernel<<<(N_TOK * DIM / 4) / 256, 256>>>(x);
    zeroout_kernel<<<(N_TOK * DIM / 4) / 256, 256>>>(out);
    gemm1_mma<<<dim3(FDIM / BN, N_TOK / BM, NEXP), 256>>>(w1, b1);
    gemm2_mma<<<dim3(DIM / BN, N_TOK / BM, NEXP), 256>>>(w2, b2, out);
}

// round 6
// speedup vs baseline: 2.3227x; 1.4410x over previous
#include <cuda_runtime.h>
#include <cuda_bf16.h>
#include <math.h>
#include <stdint.h>

#define N_TOK 4096
#define DIM   1024
#define NEXP  8
#define FDIM  2048
#define NPAIR (2*N_TOK)

// ---------------- device scratch (~80.2 MB, proven safe in R4) ----------------
__device__ int   g_cnt[NEXP];
__device__ int   g_off[NEXP];
__device__ int   g_bucket[NEXP * N_TOK];
__device__ float g_pairw[NPAIR];
__device__ __nv_bfloat16 g_xh[(size_t)N_TOK * DIM];   // 8 MB
__device__ __nv_bfloat16 g_xl[(size_t)N_TOK * DIM];   // 8 MB
__device__ __nv_bfloat16 g_hh[(size_t)NPAIR * FDIM];  // 32 MB
__device__ __nv_bfloat16 g_hl[(size_t)NPAIR * FDIM];  // 32 MB

// ==================== helpers ====================
__device__ __forceinline__ uint32_t smem_u32(const void* p) {
    uint32_t a;
    asm("{ .reg .u64 t; cvta.to.shared.u64 t, %1; cvt.u32.u64 %0, t; }" : "=r"(a) : "l"(p));
    return a;
}
#define CP16(dst, src) \
    asm volatile("cp.async.ca.shared.global [%0], [%1], 16;" :: "r"(dst), "l"(src) : "memory")
#define CP_COMMIT() asm volatile("cp.async.commit_group;" ::: "memory")
#define CP_WAIT0()  asm volatile("cp.async.wait_group 0;" ::: "memory")
#define LDSM4(r0, r1, r2, r3, addr) \
    asm volatile("ldmatrix.sync.aligned.m8n8.x4.shared.b16 {%0,%1,%2,%3}, [%4];" \
                 : "=r"(r0), "=r"(r1), "=r"(r2), "=r"(r3) : "r"(addr) : "memory")

__device__ __forceinline__ void mma_bf16(float (&c)[4], const uint32_t* a, const uint32_t* b) {
    asm volatile(
        "mma.sync.aligned.m16n8k16.row.col.f32.bf16.bf16.f32 "
        "{%0,%1,%2,%3}, {%4,%5,%6,%7}, {%8,%9}, {%0,%1,%2,%3};"
        : "+f"(c[0]), "+f"(c[1]), "+f"(c[2]), "+f"(c[3])
        : "r"(a[0]), "r"(a[1]), "r"(a[2]), "r"(a[3]), "r"(b[0]), "r"(b[1]));
}

// error-free hi split (truncate) + RN lo residual, packed as two bf16x2 words
__device__ __forceinline__ void pack2(float v0, float v1, uint32_t& hp, uint32_t& lp) {
    uint32_t u0 = __float_as_uint(v0), u1 = __float_as_uint(v1);
    float l0 = v0 - __uint_as_float(u0 & 0xffff0000u);
    float l1 = v1 - __uint_as_float(u1 & 0xffff0000u);
    hp = (u0 >> 16) | (u1 & 0xffff0000u);
    lp = (uint32_t)__bfloat16_as_ushort(__float2bfloat16(l0)) |
         ((uint32_t)__bfloat16_as_ushort(__float2bfloat16(l1)) << 16);
}

// ==================== small kernels (unchanged, proven) ====================
__global__ void zero_kernel() {
    if (threadIdx.x < NEXP) g_cnt[threadIdx.x] = 0;
}

__global__ void gate_kernel(const float* __restrict__ x,
                            const float* __restrict__ gw,
                            const float* __restrict__ gb) {
    int tok  = (blockIdx.x * blockDim.x + threadIdx.x) >> 5;
    int lane = threadIdx.x & 31;
    if (tok >= N_TOK) return;
    const float* xr = x + (size_t)tok * DIM;
    float acc[NEXP];
#pragma unroll
    for (int e = 0; e < NEXP; e++) acc[e] = 0.f;
    for (int d = lane; d < DIM; d += 32) {
        float xv = xr[d];
        const float4* g4 = reinterpret_cast<const float4*>(gw + (size_t)d * NEXP);
        float4 a = g4[0], b = g4[1];
        acc[0] += xv * a.x; acc[1] += xv * a.y; acc[2] += xv * a.z; acc[3] += xv * a.w;
        acc[4] += xv * b.x; acc[5] += xv * b.y; acc[6] += xv * b.z; acc[7] += xv * b.w;
    }
#pragma unroll
    for (int e = 0; e < NEXP; e++) {
#pragma unroll
        for (int s = 16; s > 0; s >>= 1)
            acc[e] += __shfl_xor_sync(0xffffffffu, acc[e], s);
    }
    if (lane == 0) {
        float lg[NEXP];
        float mx = -1e30f;
#pragma unroll
        for (int e = 0; e < NEXP; e++) { lg[e] = acc[e] + gb[e]; mx = fmaxf(mx, lg[e]); }
        float sum = 0.f;
#pragma unroll
        for (int e = 0; e < NEXP; e++) { lg[e] = expf(lg[e] - mx); sum += lg[e]; }
        float inv = 1.f / sum;
#pragma unroll
        for (int e = 0; e < NEXP; e++) lg[e] *= inv;
        int i0 = 0;
#pragma unroll
        for (int e = 1; e < NEXP; e++) if (lg[e] > lg[i0]) i0 = e;
        int i1 = -1;
#pragma unroll
        for (int e = 0; e < NEXP; e++)
            if (e != i0 && (i1 < 0 || lg[e] > lg[i1])) i1 = e;
        float e1 = expf(lg[i1] - lg[i0]);
        float is2 = 1.f / (1.f + e1);
        g_pairw[tok * 2 + 0] = is2;
        g_pairw[tok * 2 + 1] = e1 * is2;
        int p0 = atomicAdd(&g_cnt[i0], 1);
        g_bucket[i0 * N_TOK + p0] = tok * 2 + 0;
        int p1 = atomicAdd(&g_cnt[i1], 1);
        g_bucket[i1 * N_TOK + p1] = tok * 2 + 1;
    }
}

__global__ void prefix_kernel() {
    int s = 0;
#pragma unroll
    for (int e = 0; e < NEXP; e++) { g_off[e] = s; s += g_cnt[e]; }
}

__global__ void convx_kernel(const float* __restrict__ x) {
    size_t i = ((size_t)blockIdx.x * blockDim.x + threadIdx.x) * 4;
    float4 v = *(const float4*)(x + i);
    __nv_bfloat16 h0 = __float2bfloat16(v.x), h1 = __float2bfloat16(v.y);
    __nv_bfloat16 h2 = __float2bfloat16(v.z), h3 = __float2bfloat16(v.w);
    ushort4 hv = make_ushort4(__bfloat16_as_ushort(h0), __bfloat16_as_ushort(h1),
                              __bfloat16_as_ushort(h2), __bfloat16_as_ushort(h3));
    ushort4 lv = make_ushort4(
        __bfloat16_as_ushort(__float2bfloat16(v.x - __bfloat162float(h0))),
        __bfloat16_as_ushort(__float2bfloat16(v.y - __bfloat162float(h1))),
        __bfloat16_as_ushort(__float2bfloat16(v.z - __bfloat162float(h2))),
        __bfloat16_as_ushort(__float2bfloat16(v.w - __bfloat162float(h3))));
    *(ushort4*)(g_xh + i) = hv;
    *(ushort4*)(g_xl + i) = lv;
}

__global__ void zeroout_kernel(float* __restrict__ out) {
    size_t i = ((size_t)blockIdx.x * blockDim.x + threadIdx.x) * 4;
    *(float4*)(out + i) = make_float4(0.f, 0.f, 0.f, 0.f);
}

// ==================== GEMM config ====================
// 128x128 tile, BK=32, double-buffered smem, ldmatrix + cp.async.
// Four bf16 tiles per buffer (Ah, Al, Bh, Bl), each 128 rows x 32 bf16,
// row stride 40 bf16 = 80 B (16B-aligned, conflict-free ldmatrix phases).
#define ROWB   80
#define TILEB  (128 * ROWB)      // 10240
#define BUFB   (4 * TILEB)       // 40960
#define DSM    (2 * BUFB)        // 81920

// per-iteration compute: 2 k-steps of 16; 24 ldmatrix + 96 HMMA per chunk
#define GEMM_COMPUTE(bu)                                                          \
    _Pragma("unroll")                                                             \
    for (int ks = 0; ks < 2; ks++) {                                              \
        uint32_t bh[8], bl[8];                                                    \
        LDSM4(bh[0], bh[1], bh[2], bh[3], (bu) + 2 * TILEB + boff + ks * 32);     \
        LDSM4(bh[4], bh[5], bh[6], bh[7], (bu) + 2 * TILEB + boff + 1280 + ks * 32); \
        LDSM4(bl[0], bl[1], bl[2], bl[3], (bu) + 3 * TILEB + boff + ks * 32);     \
        LDSM4(bl[4], bl[5], bl[6], bl[7], (bu) + 3 * TILEB + boff + 1280 + ks * 32); \
        _Pragma("unroll")                                                         \
        for (int mt = 0; mt < 4; mt++) {                                          \
            uint32_t ah[4], al[4];                                                \
            LDSM4(ah[0], ah[1], ah[2], ah[3], (bu) + aoff + mt * 1280 + ks * 32); \
            LDSM4(al[0], al[1], al[2], al[3], (bu) + TILEB + aoff + mt * 1280 + ks * 32); \
            _Pragma("unroll")                                                     \
            for (int nt = 0; nt < 4; nt++) {                                      \
                mma_bf16(acc[mt][nt], ah, &bh[nt * 2]);                           \
                mma_bf16(acc[mt][nt], ah, &bl[nt * 2]);                           \
                mma_bf16(acc[mt][nt], al, &bh[nt * 2]);                           \
            }                                                                     \
        }                                                                         \
    }

// fill helpers (A via cp.async from bf16 planes; B via LDG+split+STS)
#define FILL_A_CP(bu, k0)                                                         \
    do {                                                                          \
        CP16((bu) + aDst,            (const char*)(pAh + (k0) + half * 16));      \
        CP16((bu) + aDst + 16,       (const char*)(pAh + (k0) + half * 16 + 8));  \
        CP16((bu) + TILEB + aDst,    (const char*)(pAl + (k0) + half * 16));      \
        CP16((bu) + TILEB + aDst + 16, (const char*)(pAl + (k0) + half * 16 + 8)); \
        CP_COMMIT();                                                              \
    } while (0)

#define LDG_B(k0)                                                                 \
    _Pragma("unroll")                                                             \
    for (int j = 0; j < 16; j++) stg[j] = pW[(size_t)((k0) + kh * 16 + j) * ldw];

#define STS_B(bufc)                                                               \
    do {                                                                          \
        uint32_t* hp = (uint32_t*)(dsm + (bufc) + 2 * TILEB + bDst);              \
        uint32_t* lp = (uint32_t*)(dsm + (bufc) + 3 * TILEB + bDst);              \
        _Pragma("unroll")                                                         \
        for (int j = 0; j < 8; j++) {                                             \
            uint32_t h, l;                                                        \
            pack2(stg[2 * j], stg[2 * j + 1], h, l);                              \
            hp[j] = h; lp[j] = l;                                                 \
        }                                                                         \
    } while (0)

// ---------------- gemm1: H = relu(Xg @ w1 + b1) -> bf16 hi/lo planes ------
__global__ void __launch_bounds__(256)
gemm1_tc(const float* __restrict__ w1, const float* __restrict__ b1) {
    const int e   = blockIdx.z;
    const int cnt = g_cnt[e];
    const int m0  = blockIdx.y * 128;
    if (m0 >= cnt) return;
    const int n0   = blockIdx.x * 128;
    const int base = g_off[e];
    const int tid  = threadIdx.x;
    const int wid  = tid >> 5, lane = tid & 31;

    extern __shared__ __align__(128) char dsm[];
    const uint32_t s0 = smem_u32(dsm);

    // A fill: thread -> (row, 16-elem half)
    const int ar = tid >> 1, half = tid & 1;
    const int tok = g_bucket[e * N_TOK + min(m0 + ar, cnt - 1)] >> 1;
    const __nv_bfloat16* pAh = g_xh + (size_t)tok * DIM;
    const __nv_bfloat16* pAl = g_xl + (size_t)tok * DIM;
    const uint32_t aDst = (uint32_t)(ar * ROWB + half * 32);

    // B fill: thread -> (n column, 16-k half); coalesced LDG across lanes
    const int bn = tid & 127, kh = tid >> 7;
    const int ldw = FDIM;
    const float* pW = w1 + (size_t)e * DIM * FDIM + n0 + bn;
    const uint32_t bDst = (uint32_t)(bn * ROWB + kh * 32);

    // ldmatrix per-lane offsets
    const int wm = (wid & 1) * 64, wn = (wid >> 1) * 32;
    const uint32_t aoff = s0 == s0 ?  // keep as plain expr
        (uint32_t)((wm + (lane & 7) + ((lane >> 3) & 1) * 8) * ROWB + (lane >> 4) * 16) : 0;
    const uint32_t boff =
        (uint32_t)((wn + (lane & 7) + ((lane >> 4) & 1) * 8) * ROWB + ((lane >> 3) & 1) * 16);

    float acc[4][4][4];
#pragma unroll
    for (int i = 0; i < 4; i++)
#pragma unroll
        for (int j = 0; j < 4; j++)
#pragma unroll
            for (int q = 0; q < 4; q++) acc[i][j][q] = 0.f;

    float stg[16];

    // prologue: chunk 0 -> buffer 0
    FILL_A_CP(s0, 0);
    LDG_B(0);
    STS_B(0);
    CP_WAIT0();
    __syncthreads();

    const int CH = DIM / 32;   // 32
    for (int c = 0; c < CH; c++) {
        const uint32_t bu   = s0 + (uint32_t)(c & 1) * BUFB;
        const uint32_t nxtO = (uint32_t)((c + 1) & 1) * BUFB;
        const bool more = (c + 1 < CH);
        if (more) {
            const int k0 = (c + 1) * 32;
            FILL_A_CP(s0 + nxtO, k0);
            LDG_B(k0);
        }
        GEMM_COMPUTE(bu);
        if (more) {
            STS_B(nxtO);
            CP_WAIT0();
            __syncthreads();
        }
    }

    // epilogue: +b1, relu, split to bf16 hi/lo planes
    const int gq = lane >> 2, tq = lane & 3;
#pragma unroll
    for (int nt = 0; nt < 4; nt++) {
        const int nc = n0 + wn + nt * 8 + tq * 2;
        const float bb0 = b1[e * FDIM + nc];
        const float bb1 = b1[e * FDIM + nc + 1];
#pragma unroll
        for (int mt = 0; mt < 4; mt++) {
            const int rl = wm + mt * 16 + gq;
#pragma unroll
            for (int hf = 0; hf < 2; hf++) {
                const int gr = m0 + rl + hf * 8;
                if (gr < cnt) {
                    float v0 = fmaxf(acc[mt][nt][hf * 2 + 0] + bb0, 0.f);
                    float v1 = fmaxf(acc[mt][nt][hf * 2 + 1] + bb1, 0.f);
                    size_t o = (size_t)(base + gr) * FDIM + nc;
                    __nv_bfloat16 h0 = __float2bfloat16(v0), h1 = __float2bfloat16(v1);
                    __nv_bfloat162 hv; hv.x = h0; hv.y = h1;
                    __nv_bfloat162 lv;
                    lv.x = __float2bfloat16(v0 - __bfloat162float(h0));
                    lv.y = __float2bfloat16(v1 - __bfloat162float(h1));
                    *(__nv_bfloat162*)&g_hh[o] = hv;
                    *(__nv_bfloat162*)&g_hl[o] = lv;
                }
            }
        }
    }
}

// ---------------- gemm2: out += (H @ w2 + b2) * pairw (atomic) ------------
__global__ void __launch_bounds__(256)
gemm2_tc(const float* __restrict__ w2, const float* __restrict__ b2,
         float* __restrict__ out) {
    const int e   = blockIdx.z;
    const int cnt = g_cnt[e];
    const int m0  = blockIdx.y * 128;
    if (m0 >= cnt) return;
    const int n0   = blockIdx.x * 128;
    const int base = g_off[e];
    const int tid  = threadIdx.x;
    const int wid  = tid >> 5, lane = tid & 31;

    extern __shared__ __align__(128) char dsm[];
    const uint32_t s0 = smem_u32(dsm);

    const int ar = tid >> 1, half = tid & 1;
    const size_t arow = (size_t)(base + min(m0 + ar, cnt - 1)) * FDIM;
    const __nv_bfloat16* pAh = g_hh + arow;
    const __nv_bfloat16* pAl = g_hl + arow;
    const uint32_t aDst = (uint32_t)(ar * ROWB + half * 32);

    const int bn = tid & 127, kh = tid >> 7;
    const int ldw = DIM;
    const float* pW = w2 + (size_t)e * FDIM * DIM + n0 + bn;
    const uint32_t bDst = (uint32_t)(bn * ROWB + kh * 32);

    const int wm = (wid & 1) * 64, wn = (wid >> 1) * 32;
    const uint32_t aoff =
        (uint32_t)((wm + (lane & 7) + ((lane >> 3) & 1) * 8) * ROWB + (lane >> 4) * 16);
    const uint32_t boff =
        (uint32_t)((wn + (lane & 7) + ((lane >> 4) & 1) * 8) * ROWB + ((lane >> 3) & 1) * 16);

    float acc[4][4][4];
#pragma unroll
    for (int i = 0; i < 4; i++)
#pragma unroll
        for (int j = 0; j < 4; j++)
#pragma unroll
            for (int q = 0; q < 4; q++) acc[i][j][q] = 0.f;

    float stg[16];

    FILL_A_CP(s0, 0);
    LDG_B(0);
    STS_B(0);
    CP_WAIT0();
    __syncthreads();

    const int CH = FDIM / 32;   // 64
    for (int c = 0; c < CH; c++) {
        const uint32_t bu   = s0 + (uint32_t)(c & 1) * BUFB;
        const uint32_t nxtO = (uint32_t)((c + 1) & 1) * BUFB;
        const bool more = (c + 1 < CH);
        if (more) {
            const int k0 = (c + 1) * 32;
            FILL_A_CP(s0 + nxtO, k0);
            LDG_B(k0);
        }
        GEMM_COMPUTE(bu);
        if (more) {
            STS_B(nxtO);
            CP_WAIT0();
            __syncthreads();
        }
    }

    // epilogue: (+b2) * combine weight, atomicAdd into out (2 adds/element,
    // commutative fp32 add -> bitwise deterministic)
    const int gq = lane >> 2, tq = lane & 3;
#pragma unroll
    for (int nt = 0; nt < 4; nt++) {
        const int nc = n0 + wn + nt * 8 + tq * 2;
        const float bb0 = b2[e * DIM + nc];
        const float bb1 = b2[e * DIM + nc + 1];
#pragma unroll
        for (int mt = 0; mt < 4; mt++) {
            const int rl = wm + mt * 16 + gq;
#pragma unroll
            for (int hf = 0; hf < 2; hf++) {
                const int gr = m0 + rl + hf * 8;
                if (gr < cnt) {
                    const int p = g_bucket[e * N_TOK + gr];
                    const float w = g_pairw[p];
                    float* orow = out + (size_t)(p >> 1) * DIM + nc;
                    atomicAdd(orow,     (acc[mt][nt][hf * 2 + 0] + bb0) * w);
                    atomicAdd(orow + 1, (acc[mt][nt][hf * 2 + 1] + bb1) * w);
                }
            }
        }
    }
}

// ---------------- launch ----------------
extern "C" void kernel_launch(void* const* d_in, const int* in_sizes, int n_in,
                              void* d_out, int out_size) {
    const float* x  = (const float*)d_in[0];
    const float* gw = (const float*)d_in[1];
    const float* gb = (const float*)d_in[2];
    const float* w1 = (const float*)d_in[3];
    const float* b1 = (const float*)d_in[4];
    const float* w2 = (const float*)d_in[5];
    const float* b2 = (const float*)d_in[6];
    float* out = (float*)d_out;

    cudaFuncSetAttribute(gemm1_tc, cudaFuncAttributeMaxDynamicSharedMemorySize, DSM);
    cudaFuncSetAttribute(gemm2_tc, cudaFuncAttributeMaxDynamicSharedMemorySize, DSM);

    zero_kernel<<<1, 32>>>();
    gate_kernel<<<N_TOK / 8, 256>>>(x, gw, gb);
    prefix_kernel<<<1, 1>>>();
    convx_kernel<<<(N_TOK * DIM / 4) / 256, 256>>>(x);
    zeroout_kernel<<<(N_TOK * DIM / 4) / 256, 256>>>(out);
    gemm1_tc<<<dim3(FDIM / 128, N_TOK / 128, NEXP), 256, DSM>>>(w1, b1);
    gemm2_tc<<<dim3(DIM / 128, N_TOK / 128, NEXP), 256, DSM>>>(w2, b2, out);
}

// round 7
// speedup vs baseline: 2.3761x; 1.0230x over previous
#include <cuda_runtime.h>
#include <cuda_bf16.h>
#include <math.h>
#include <stdint.h>

#define N_TOK 4096
#define DIM   1024
#define NEXP  8
#define FDIM  2048
#define NPAIR (2*N_TOK)

// ---------------- device scratch (~80.2 MB, proven safe) ----------------
__device__ int   g_cnt[NEXP];
__device__ int   g_off[NEXP];
__device__ int   g_bucket[NEXP * N_TOK];
__device__ float g_pairw[NPAIR];
__device__ __nv_bfloat16 g_xh[(size_t)N_TOK * DIM];   // 8 MB
__device__ __nv_bfloat16 g_xl[(size_t)N_TOK * DIM];   // 8 MB
__device__ __nv_bfloat16 g_hh[(size_t)NPAIR * FDIM];  // 32 MB
__device__ __nv_bfloat16 g_hl[(size_t)NPAIR * FDIM];  // 32 MB

// ==================== helpers ====================
__device__ __forceinline__ uint32_t smem_u32(const void* p) {
    uint32_t a;
    asm("{ .reg .u64 t; cvta.to.shared.u64 t, %1; cvt.u32.u64 %0, t; }" : "=r"(a) : "l"(p));
    return a;
}
#define CP16(dst, src) \
    asm volatile("cp.async.ca.shared.global [%0], [%1], 16;" :: "r"(dst), "l"(src) : "memory")
#define CP_COMMIT() asm volatile("cp.async.commit_group;" ::: "memory")
#define CP_WAIT0()  asm volatile("cp.async.wait_group 0;" ::: "memory")
#define LDSM4(r0, r1, r2, r3, addr) \
    asm volatile("ldmatrix.sync.aligned.m8n8.x4.shared.b16 {%0,%1,%2,%3}, [%4];" \
                 : "=r"(r0), "=r"(r1), "=r"(r2), "=r"(r3) : "r"(addr) : "memory")

__device__ __forceinline__ void mma_bf16(float (&c)[4], const uint32_t* a, const uint32_t* b) {
    asm volatile(
        "mma.sync.aligned.m16n8k16.row.col.f32.bf16.bf16.f32 "
        "{%0,%1,%2,%3}, {%4,%5,%6,%7}, {%8,%9}, {%0,%1,%2,%3};"
        : "+f"(c[0]), "+f"(c[1]), "+f"(c[2]), "+f"(c[3])
        : "r"(a[0]), "r"(a[1]), "r"(a[2]), "r"(a[3]), "r"(b[0]), "r"(b[1]));
}

// error-free hi split (truncate) + RN lo residual, packed as two bf16x2 words
__device__ __forceinline__ void pack2(float v0, float v1, uint32_t& hp, uint32_t& lp) {
    uint32_t u0 = __float_as_uint(v0), u1 = __float_as_uint(v1);
    float l0 = v0 - __uint_as_float(u0 & 0xffff0000u);
    float l1 = v1 - __uint_as_float(u1 & 0xffff0000u);
    hp = (u0 >> 16) | (u1 & 0xffff0000u);
    lp = (uint32_t)__bfloat16_as_ushort(__float2bfloat16(l0)) |
         ((uint32_t)__bfloat16_as_ushort(__float2bfloat16(l1)) << 16);
}

// ==================== small kernels ====================
__global__ void zero_kernel() {
    if (threadIdx.x < NEXP) g_cnt[threadIdx.x] = 0;
}

__global__ void gate_kernel(const float* __restrict__ x,
                            const float* __restrict__ gw,
                            const float* __restrict__ gb) {
    int tok  = (blockIdx.x * blockDim.x + threadIdx.x) >> 5;
    int lane = threadIdx.x & 31;
    if (tok >= N_TOK) return;
    const float* xr = x + (size_t)tok * DIM;
    float acc[NEXP];
#pragma unroll
    for (int e = 0; e < NEXP; e++) acc[e] = 0.f;
    for (int d = lane; d < DIM; d += 32) {
        float xv = xr[d];
        const float4* g4 = reinterpret_cast<const float4*>(gw + (size_t)d * NEXP);
        float4 a = g4[0], b = g4[1];
        acc[0] += xv * a.x; acc[1] += xv * a.y; acc[2] += xv * a.z; acc[3] += xv * a.w;
        acc[4] += xv * b.x; acc[5] += xv * b.y; acc[6] += xv * b.z; acc[7] += xv * b.w;
    }
#pragma unroll
    for (int e = 0; e < NEXP; e++) {
#pragma unroll
        for (int s = 16; s > 0; s >>= 1)
            acc[e] += __shfl_xor_sync(0xffffffffu, acc[e], s);
    }
    if (lane == 0) {
        float lg[NEXP];
        float mx = -1e30f;
#pragma unroll
        for (int e = 0; e < NEXP; e++) { lg[e] = acc[e] + gb[e]; mx = fmaxf(mx, lg[e]); }
        float sum = 0.f;
#pragma unroll
        for (int e = 0; e < NEXP; e++) { lg[e] = expf(lg[e] - mx); sum += lg[e]; }
        float inv = 1.f / sum;
#pragma unroll
        for (int e = 0; e < NEXP; e++) lg[e] *= inv;
        int i0 = 0;
#pragma unroll
        for (int e = 1; e < NEXP; e++) if (lg[e] > lg[i0]) i0 = e;
        int i1 = -1;
#pragma unroll
        for (int e = 0; e < NEXP; e++)
            if (e != i0 && (i1 < 0 || lg[e] > lg[i1])) i1 = e;
        float e1 = expf(lg[i1] - lg[i0]);
        float is2 = 1.f / (1.f + e1);
        g_pairw[tok * 2 + 0] = is2;
        g_pairw[tok * 2 + 1] = e1 * is2;
        int p0 = atomicAdd(&g_cnt[i0], 1);
        g_bucket[i0 * N_TOK + p0] = tok * 2 + 0;
        int p1 = atomicAdd(&g_cnt[i1], 1);
        g_bucket[i1 * N_TOK + p1] = tok * 2 + 1;
    }
}

__global__ void prefix_kernel() {
    int s = 0;
#pragma unroll
    for (int e = 0; e < NEXP; e++) { g_off[e] = s; s += g_cnt[e]; }
}

// convx + zero-out fused (same index space)
__global__ void convx_kernel(const float* __restrict__ x, float* __restrict__ out) {
    size_t i = ((size_t)blockIdx.x * blockDim.x + threadIdx.x) * 4;
    float4 v = *(const float4*)(x + i);
    __nv_bfloat16 h0 = __float2bfloat16(v.x), h1 = __float2bfloat16(v.y);
    __nv_bfloat16 h2 = __float2bfloat16(v.z), h3 = __float2bfloat16(v.w);
    ushort4 hv = make_ushort4(__bfloat16_as_ushort(h0), __bfloat16_as_ushort(h1),
                              __bfloat16_as_ushort(h2), __bfloat16_as_ushort(h3));
    ushort4 lv = make_ushort4(
        __bfloat16_as_ushort(__float2bfloat16(v.x - __bfloat162float(h0))),
        __bfloat16_as_ushort(__float2bfloat16(v.y - __bfloat162float(h1))),
        __bfloat16_as_ushort(__float2bfloat16(v.z - __bfloat162float(h2))),
        __bfloat16_as_ushort(__float2bfloat16(v.w - __bfloat162float(h3))));
    *(ushort4*)(g_xh + i) = hv;
    *(ushort4*)(g_xl + i) = lv;
    *(float4*)(out + i) = make_float4(0.f, 0.f, 0.f, 0.f);
}

// ==================== GEMM config ====================
// 128x128 tile, BK=32, double-buffered smem, ldmatrix + cp.async, 2 CTAs/SM.
#define ROWB   80
#define TILEB  (128 * ROWB)      // 10240
#define BUFB   (4 * TILEB)       // 40960
#define DSM    (2 * BUFB)        // 81920

#define GEMM_COMPUTE(bu)                                                          \
    _Pragma("unroll")                                                             \
    for (int ks = 0; ks < 2; ks++) {                                              \
        uint32_t bh[8], bl[8];                                                    \
        LDSM4(bh[0], bh[1], bh[2], bh[3], (bu) + 2 * TILEB + boff + ks * 32);     \
        LDSM4(bh[4], bh[5], bh[6], bh[7], (bu) + 2 * TILEB + boff + 1280 + ks * 32); \
        LDSM4(bl[0], bl[1], bl[2], bl[3], (bu) + 3 * TILEB + boff + ks * 32);     \
        LDSM4(bl[4], bl[5], bl[6], bl[7], (bu) + 3 * TILEB + boff + 1280 + ks * 32); \
        _Pragma("unroll")                                                         \
        for (int mt = 0; mt < 4; mt++) {                                          \
            uint32_t ah[4], al[4];                                                \
            LDSM4(ah[0], ah[1], ah[2], ah[3], (bu) + aoff + mt * 1280 + ks * 32); \
            LDSM4(al[0], al[1], al[2], al[3], (bu) + TILEB + aoff + mt * 1280 + ks * 32); \
            _Pragma("unroll")                                                     \
            for (int nt = 0; nt < 4; nt++) {                                      \
                mma_bf16(acc[mt][nt], ah, &bh[nt * 2]);                           \
                mma_bf16(acc[mt][nt], ah, &bl[nt * 2]);                           \
                mma_bf16(acc[mt][nt], al, &bh[nt * 2]);                           \
            }                                                                     \
        }                                                                         \
    }

#define FILL_A_CP(bu, k0)                                                         \
    do {                                                                          \
        CP16((bu) + aDst,            (const char*)(pAh + (k0) + half * 16));      \
        CP16((bu) + aDst + 16,       (const char*)(pAh + (k0) + half * 16 + 8));  \
        CP16((bu) + TILEB + aDst,    (const char*)(pAl + (k0) + half * 16));      \
        CP16((bu) + TILEB + aDst + 16, (const char*)(pAl + (k0) + half * 16 + 8)); \
        CP_COMMIT();                                                              \
    } while (0)

#define LDG_B(k0)                                                                 \
    _Pragma("unroll")                                                             \
    for (int j = 0; j < 16; j++) stg[j] = pW[(size_t)((k0) + kh * 16 + j) * ldw];

#define STS_B(bufc)                                                               \
    do {                                                                          \
        uint32_t* hp = (uint32_t*)(dsm + (bufc) + 2 * TILEB + bDst);              \
        uint32_t* lp = (uint32_t*)(dsm + (bufc) + 3 * TILEB + bDst);              \
        _Pragma("unroll")                                                         \
        for (int j = 0; j < 8; j++) {                                             \
            uint32_t h, l;                                                        \
            pack2(stg[2 * j], stg[2 * j + 1], h, l);                              \
            hp[j] = h; lp[j] = l;                                                 \
        }                                                                         \
    } while (0)

// ---------------- gemm1: H = relu(Xg @ w1 + b1) -> bf16 hi/lo planes ------
__global__ void __launch_bounds__(256, 2)
gemm1_tc(const float* __restrict__ w1, const float* __restrict__ b1) {
    const int e   = blockIdx.z;
    const int cnt = g_cnt[e];
    const int m0  = blockIdx.y * 128;
    if (m0 >= cnt) return;
    const int n0   = blockIdx.x * 128;
    const int base = g_off[e];
    const int tid  = threadIdx.x;
    const int wid  = tid >> 5, lane = tid & 31;

    extern __shared__ __align__(128) char dsm[];
    const uint32_t s0 = smem_u32(dsm);

    const int ar = tid >> 1, half = tid & 1;
    const int tok = g_bucket[e * N_TOK + min(m0 + ar, cnt - 1)] >> 1;
    const __nv_bfloat16* pAh = g_xh + (size_t)tok * DIM;
    const __nv_bfloat16* pAl = g_xl + (size_t)tok * DIM;
    const uint32_t aDst = (uint32_t)(ar * ROWB + half * 32);

    const int bn = tid & 127, kh = tid >> 7;
    const int ldw = FDIM;
    const float* pW = w1 + (size_t)e * DIM * FDIM + n0 + bn;
    const uint32_t bDst = (uint32_t)(bn * ROWB + kh * 32);

    const int wm = (wid & 1) * 64, wn = (wid >> 1) * 32;
    const uint32_t aoff =
        (uint32_t)((wm + (lane & 7) + ((lane >> 3) & 1) * 8) * ROWB + (lane >> 4) * 16);
    const uint32_t boff =
        (uint32_t)((wn + (lane & 7) + ((lane >> 4) & 1) * 8) * ROWB + ((lane >> 3) & 1) * 16);

    float acc[4][4][4];
#pragma unroll
    for (int i = 0; i < 4; i++)
#pragma unroll
        for (int j = 0; j < 4; j++)
#pragma unroll
            for (int q = 0; q < 4; q++) acc[i][j][q] = 0.f;

    float stg[16];

    FILL_A_CP(s0, 0);
    LDG_B(0);
    STS_B(0);
    CP_WAIT0();
    __syncthreads();

    const int CH = DIM / 32;   // 32
    for (int c = 0; c < CH; c++) {
        const uint32_t bu   = s0 + (uint32_t)(c & 1) * BUFB;
        const uint32_t nxtO = (uint32_t)((c + 1) & 1) * BUFB;
        const bool more = (c + 1 < CH);
        if (more) {
            const int k0 = (c + 1) * 32;
            FILL_A_CP(s0 + nxtO, k0);
            LDG_B(k0);
        }
        GEMM_COMPUTE(bu);
        if (more) {
            STS_B(nxtO);
            CP_WAIT0();
            __syncthreads();
        }
    }

    const int gq = lane >> 2, tq = lane & 3;
#pragma unroll
    for (int nt = 0; nt < 4; nt++) {
        const int nc = n0 + wn + nt * 8 + tq * 2;
        const float bb0 = b1[e * FDIM + nc];
        const float bb1 = b1[e * FDIM + nc + 1];
#pragma unroll
        for (int mt = 0; mt < 4; mt++) {
            const int rl = wm + mt * 16 + gq;
#pragma unroll
            for (int hf = 0; hf < 2; hf++) {
                const int gr = m0 + rl + hf * 8;
                if (gr < cnt) {
                    float v0 = fmaxf(acc[mt][nt][hf * 2 + 0] + bb0, 0.f);
                    float v1 = fmaxf(acc[mt][nt][hf * 2 + 1] + bb1, 0.f);
                    size_t o = (size_t)(base + gr) * FDIM + nc;
                    __nv_bfloat16 h0 = __float2bfloat16(v0), h1 = __float2bfloat16(v1);
                    __nv_bfloat162 hv; hv.x = h0; hv.y = h1;
                    __nv_bfloat162 lv;
                    lv.x = __float2bfloat16(v0 - __bfloat162float(h0));
                    lv.y = __float2bfloat16(v1 - __bfloat162float(h1));
                    *(__nv_bfloat162*)&g_hh[o] = hv;
                    *(__nv_bfloat162*)&g_hl[o] = lv;
                }
            }
        }
    }
}

// ---------------- gemm2: out += (H @ w2 + b2) * pairw (atomic) ------------
__global__ void __launch_bounds__(256, 2)
gemm2_tc(const float* __restrict__ w2, const float* __restrict__ b2,
         float* __restrict__ out) {
    const int e   = blockIdx.z;
    const int cnt = g_cnt[e];
    const int m0  = blockIdx.y * 128;
    if (m0 >= cnt) return;
    const int n0   = blockIdx.x * 128;
    const int base = g_off[e];
    const int tid  = threadIdx.x;
    const int wid  = tid >> 5, lane = tid & 31;

    extern __shared__ __align__(128) char dsm[];
    const uint32_t s0 = smem_u32(dsm);

    const int ar = tid >> 1, half = tid & 1;
    const size_t arow = (size_t)(base + min(m0 + ar, cnt - 1)) * FDIM;
    const __nv_bfloat16* pAh = g_hh + arow;
    const __nv_bfloat16* pAl = g_hl + arow;
    const uint32_t aDst = (uint32_t)(ar * ROWB + half * 32);

    const int bn = tid & 127, kh = tid >> 7;
    const int ldw = DIM;
    const float* pW = w2 + (size_t)e * FDIM * DIM + n0 + bn;
    const uint32_t bDst = (uint32_t)(bn * ROWB + kh * 32);

    const int wm = (wid & 1) * 64, wn = (wid >> 1) * 32;
    const uint32_t aoff =
        (uint32_t)((wm + (lane & 7) + ((lane >> 3) & 1) * 8) * ROWB + (lane >> 4) * 16);
    const uint32_t boff =
        (uint32_t)((wn + (lane & 7) + ((lane >> 4) & 1) * 8) * ROWB + ((lane >> 3) & 1) * 16);

    float acc[4][4][4];
#pragma unroll
    for (int i = 0; i < 4; i++)
#pragma unroll
        for (int j = 0; j < 4; j++)
#pragma unroll
            for (int q = 0; q < 4; q++) acc[i][j][q] = 0.f;

    float stg[16];

    FILL_A_CP(s0, 0);
    LDG_B(0);
    STS_B(0);
    CP_WAIT0();
    __syncthreads();

    const int CH = FDIM / 32;   // 64
    for (int c = 0; c < CH; c++) {
        const uint32_t bu   = s0 + (uint32_t)(c & 1) * BUFB;
        const uint32_t nxtO = (uint32_t)((c + 1) & 1) * BUFB;
        const bool more = (c + 1 < CH);
        if (more) {
            const int k0 = (c + 1) * 32;
            FILL_A_CP(s0 + nxtO, k0);
            LDG_B(k0);
        }
        GEMM_COMPUTE(bu);
        if (more) {
            STS_B(nxtO);
            CP_WAIT0();
            __syncthreads();
        }
    }

    // epilogue: (+b2) * combine weight, atomicAdd into out (2 adds/element,
    // commutative fp32 add -> bitwise deterministic)
    const int gq = lane >> 2, tq = lane & 3;
#pragma unroll
    for (int nt = 0; nt < 4; nt++) {
        const int nc = n0 + wn + nt * 8 + tq * 2;
        const float bb0 = b2[e * DIM + nc];
        const float bb1 = b2[e * DIM + nc + 1];
#pragma unroll
        for (int mt = 0; mt < 4; mt++) {
            const int rl = wm + mt * 16 + gq;
#pragma unroll
            for (int hf = 0; hf < 2; hf++) {
                const int gr = m0 + rl + hf * 8;
                if (gr < cnt) {
                    const int p = g_bucket[e * N_TOK + gr];
                    const float w = g_pairw[p];
                    float* orow = out + (size_t)(p >> 1) * DIM + nc;
                    atomicAdd(orow,     (acc[mt][nt][hf * 2 + 0] + bb0) * w);
                    atomicAdd(orow + 1, (acc[mt][nt][hf * 2 + 1] + bb1) * w);
                }
            }
        }
    }
}

// ---------------- launch ----------------
extern "C" void kernel_launch(void* const* d_in, const int* in_sizes, int n_in,
                              void* d_out, int out_size) {
    const float* x  = (const float*)d_in[0];
    const float* gw = (const float*)d_in[1];
    const float* gb = (const float*)d_in[2];
    const float* w1 = (const float*)d_in[3];
    const float* b1 = (const float*)d_in[4];
    const float* w2 = (const float*)d_in[5];
    const float* b2 = (const float*)d_in[6];
    float* out = (float*)d_out;

    cudaFuncSetAttribute(gemm1_tc, cudaFuncAttributeMaxDynamicSharedMemorySize, DSM);
    cudaFuncSetAttribute(gemm2_tc, cudaFuncAttributeMaxDynamicSharedMemorySize, DSM);

    zero_kernel<<<1, 32>>>();
    gate_kernel<<<N_TOK / 8, 256>>>(x, gw, gb);
    prefix_kernel<<<1, 1>>>();
    convx_kernel<<<(N_TOK * DIM / 4) / 256, 256>>>(x, out);
    gemm1_tc<<<dim3(FDIM / 128, N_TOK / 128, NEXP), 256, DSM>>>(w1, b1);
    gemm2_tc<<<dim3(DIM / 128, N_TOK / 128, NEXP), 256, DSM>>>(w2, b2, out);
}